// round 3
// baseline (speedup 1.0000x reference)
#include <cuda_runtime.h>
#include <math.h>

#define N     8192
#define FIN   64
#define HID   64
#define HEADS 2
#define C     16

// ---------------- scratch (static device globals; no allocation) ----------------
__device__ float g_Wh[HEADS][N][HID];      // 4 MB   per-head Wh = x @ W_h
__device__ float g_u[HEADS][N], g_v[HEADS][N];
__device__ float g_A[HEADS][N], g_A5K[HEADS][N], g_B[HEADS][N], g_B5[HEADS][N];
__device__ float g_h[N][HEADS * HID];      // 4 MB   concat of layer-1 head outputs
__device__ float g_Wh2[N][C];
__device__ float g_u2[N], g_v2[N];
__device__ float g_A2[N], g_A5K2[N], g_B2[N], g_B52[N];
__device__ float g_max[8];                 // [0]=u1max [1]=v1max [2]=u2max [3]=v2max [4]=uo [5]=vo

// ---------------- K1: Wh_h = x @ W_h  (64-row tiles) ----------------
__global__ void k_gemm1(const float* __restrict__ x, const float* __restrict__ W_heads) {
    __shared__ float xs[64][FIN];    // 16 KB
    __shared__ float ws[FIN][HID];   // 16 KB
    const int h  = blockIdx.y;
    const int i0 = blockIdx.x * 64;
    const int tid = threadIdx.x;     // 256

    const float4* xg = (const float4*)(x + (size_t)i0 * FIN);
    const float4* wg = (const float4*)(W_heads + (size_t)h * FIN * HID);
#pragma unroll
    for (int it = 0; it < 4; it++) ((float4*)xs)[tid + it * 256] = xg[tid + it * 256];
#pragma unroll
    for (int it = 0; it < 4; it++) ((float4*)ws)[tid + it * 256] = wg[tid + it * 256];
    __syncthreads();

    const int f  = (tid & 15) * 4;
    const int ig = tid >> 4;         // 0..15 -> rows ig*4 ..
    float acc[4][4] = {};
#pragma unroll 4
    for (int k = 0; k < FIN; k++) {
        float4 wv = *(const float4*)&ws[k][f];
#pragma unroll
        for (int r = 0; r < 4; r++) {
            float xv = xs[ig * 4 + r][k];
            acc[r][0] = fmaf(xv, wv.x, acc[r][0]);
            acc[r][1] = fmaf(xv, wv.y, acc[r][1]);
            acc[r][2] = fmaf(xv, wv.z, acc[r][2]);
            acc[r][3] = fmaf(xv, wv.w, acc[r][3]);
        }
    }
#pragma unroll
    for (int r = 0; r < 4; r++)
        *(float4*)&g_Wh[h][i0 + ig * 4 + r][f] =
            make_float4(acc[r][0], acc[r][1], acc[r][2], acc[r][3]);
}

// ---------------- K2: u_i = Wh_i . a[:H], v_i = Wh_i . a[H:] ----------------
__global__ void k_uv1(const float* __restrict__ a_heads) {
    const int h    = blockIdx.y;
    const int wid  = threadIdx.x >> 5, lane = threadIdx.x & 31;
    const int i    = blockIdx.x * 8 + wid;
    const float* a   = a_heads + (size_t)h * 2 * HID;
    const float* whr = &g_Wh[h][i][0];
    float pu = fmaf(whr[lane], a[lane], whr[lane + 32] * a[lane + 32]);
    float pv = fmaf(whr[lane], a[HID + lane], whr[lane + 32] * a[HID + lane + 32]);
#pragma unroll
    for (int o = 16; o; o >>= 1) {
        pu += __shfl_xor_sync(0xffffffffu, pu, o);
        pv += __shfl_xor_sync(0xffffffffu, pv, o);
    }
    if (lane == 0) { g_u[h][i] = pu; g_v[h][i] = pv; }
}

// ---------------- K3: global max of u/v arrays ----------------
__global__ void k_max(int base) {
    const int which = base + blockIdx.x;
    const float* src =
        (which == 0) ? g_u[0] : (which == 1) ? g_v[0] :
        (which == 2) ? g_u[1] : (which == 3) ? g_v[1] :
        (which == 4) ? g_u2   : g_v2;
    __shared__ float red[32];
    float m = -3.0e38f;
    for (int i = threadIdx.x; i < N; i += blockDim.x) m = fmaxf(m, src[i]);
#pragma unroll
    for (int o = 16; o; o >>= 1) m = fmaxf(m, __shfl_xor_sync(0xffffffffu, m, o));
    if ((threadIdx.x & 31) == 0) red[threadIdx.x >> 5] = m;
    __syncthreads();
    if (threadIdx.x < 32) {
        float mm = red[threadIdx.x];
#pragma unroll
        for (int o = 16; o; o >>= 1) mm = fmaxf(mm, __shfl_xor_sync(0xffffffffu, mm, o));
        if (threadIdx.x == 0) g_max[which] = mm;
    }
}

// ---------------- K4: exp tables (layer 1) ----------------
__global__ void k_exp1() {
    const int i = blockIdx.x * 256 + threadIdx.x;
    const int h = blockIdx.y;
    const float um = g_max[h * 2 + 0], vm = g_max[h * 2 + 1];
    const float c = um + vm;
    const float u = g_u[h][i], v = g_v[h][i];
    g_A[h][i]   = expf(u - um);
    g_A5K[h][i] = expf(0.2f * (u - um) - 0.8f * c);
    g_B[h][i]   = expf(v - vm);
    g_B5[h][i]  = expf(0.2f * (v - vm));
}

// ---------------- K5: layer-1 attention (2 heads fused), 64 rows / block ----------------
__launch_bounds__(256, 1)
__global__ void k_attn1(const int* __restrict__ adj) {
    __shared__ float w1s[64][32];      // 8 KB
    __shared__ float w2s[64][32];      // 8 KB
    __shared__ float whs[32][128];     // 16 KB  (head-concat Wh tile)
    __shared__ float rowd[6][64];      // u1,A1,A5K1,u2,A2,A5K2

    const int tid = threadIdx.x;
    const int wb = tid >> 5, lane = tid & 31;
    const int i0 = blockIdx.x * 64;
    const int head = lane >> 4;        // lanes 0-15: head0 feats, 16-31: head1 feats

    if (tid < 64) {
        rowd[0][tid] = g_u[0][i0 + tid];
        rowd[1][tid] = g_A[0][i0 + tid];
        rowd[2][tid] = g_A5K[0][i0 + tid];
        rowd[3][tid] = g_u[1][i0 + tid];
        rowd[4][tid] = g_A[1][i0 + tid];
        rowd[5][tid] = g_A5K[1][i0 + tid];
    }

    float acc[8][4] = {};
    float Zp1[8] = {}, Zp2[8] = {};

    int   adjv[8];
    float4 whv[4];
    float v1j, B1j, B51j, v2j, B2j, B52j;

    const int rowbase = i0 + wb * 8;

    // prefetch tile 0
    {
        const int j0 = 0, jc = j0 + lane;
#pragma unroll
        for (int r = 0; r < 8; r++) adjv[r] = adj[(rowbase + r) * N + jc];
        v1j = g_v[0][jc]; B1j = g_B[0][jc]; B51j = g_B5[0][jc];
        v2j = g_v[1][jc]; B2j = g_B[1][jc]; B52j = g_B5[1][jc];
#pragma unroll
        for (int it = 0; it < 4; it++) {
            int idx = tid + it * 256;
            int jj = idx >> 5, ff = (idx & 31) * 4;
            const float* src = (ff < 64) ? &g_Wh[0][j0 + jj][ff] : &g_Wh[1][j0 + jj][ff - 64];
            whv[it] = *(const float4*)src;
        }
    }

    const float* wsel = head ? &w2s[0][0] : &w1s[0][0];
    const float* wrow = wsel + wb * 8 * 32;
    const float* whp  = &whs[0][0] + (lane << 2);

    const int T = N / 32;  // 256 tiles
    for (int t = 0; t < T; t++) {
        __syncthreads();   // prev phase-B done; SMEM free

        // ---- phase A: stage Wh tile + materialize w tiles ----
#pragma unroll
        for (int it = 0; it < 4; it++) {
            int idx = tid + it * 256;
            int jj = idx >> 5, ff = (idx & 31) * 4;
            *(float4*)&whs[jj][ff] = whv[it];
        }
#pragma unroll
        for (int r = 0; r < 8; r++) {
            const int r8 = wb * 8 + r;
            const bool m = (adjv[r] != 0);
            float w1 = 0.f, w2 = 0.f;
            if (m) {
                w1 = (rowd[0][r8] + v1j > 0.f) ? rowd[1][r8] * B1j : rowd[2][r8] * B51j;
                w2 = (rowd[3][r8] + v2j > 0.f) ? rowd[4][r8] * B2j : rowd[5][r8] * B52j;
            }
            w1s[r8][lane] = w1; Zp1[r] += w1;
            w2s[r8][lane] = w2; Zp2[r] += w2;
        }

        // ---- prefetch t+1 (overlaps phase B) ----
        if (t + 1 < T) {
            const int j0 = (t + 1) * 32, jc = j0 + lane;
#pragma unroll
            for (int r = 0; r < 8; r++) adjv[r] = adj[(rowbase + r) * N + jc];
            v1j = g_v[0][jc]; B1j = g_B[0][jc]; B51j = g_B5[0][jc];
            v2j = g_v[1][jc]; B2j = g_B[1][jc]; B52j = g_B5[1][jc];
#pragma unroll
            for (int it = 0; it < 4; it++) {
                int idx = tid + it * 256;
                int jj = idx >> 5, ff = (idx & 31) * 4;
                const float* src = (ff < 64) ? &g_Wh[0][j0 + jj][ff] : &g_Wh[1][j0 + jj][ff - 64];
                whv[it] = *(const float4*)src;
            }
        }

        __syncthreads();   // w/wh tiles ready

        // ---- phase B: acc[8 rows][4 feats] += w * Wh ----
#pragma unroll 8
        for (int jj = 0; jj < 32; jj++) {
            float4 wh = *(const float4*)(whp + (jj << 7));
#pragma unroll
            for (int r = 0; r < 8; r++) {
                float w = wrow[(r << 5) + jj];
                acc[r][0] = fmaf(w, wh.x, acc[r][0]);
                acc[r][1] = fmaf(w, wh.y, acc[r][1]);
                acc[r][2] = fmaf(w, wh.z, acc[r][2]);
                acc[r][3] = fmaf(w, wh.w, acc[r][3]);
            }
        }
    }

    // ---- epilogue: reduce Z, normalize, write h_cat ----
#pragma unroll
    for (int r = 0; r < 8; r++) {
#pragma unroll
        for (int o = 16; o; o >>= 1) {
            Zp1[r] += __shfl_xor_sync(0xffffffffu, Zp1[r], o);
            Zp2[r] += __shfl_xor_sync(0xffffffffu, Zp2[r], o);
        }
    }
#pragma unroll
    for (int r = 0; r < 8; r++) {
        float Z = head ? Zp2[r] : Zp1[r];
        float inv = 1.0f / Z;
        *(float4*)&g_h[rowbase + r][lane * 4] =
            make_float4(acc[r][0] * inv, acc[r][1] * inv, acc[r][2] * inv, acc[r][3] * inv);
    }
}

// ---------------- K6: Wh2 = h_cat @ W_out ----------------
__global__ void k_gemm2(const float* __restrict__ W_out) {
    __shared__ float hs[16][HEADS * HID];  // 8 KB
    __shared__ float ws[HEADS * HID][C];   // 8 KB
    const int tid = threadIdx.x;
    const int i0 = blockIdx.x * 16;
#pragma unroll
    for (int it = 0; it < 2; it++)
        ((float4*)hs)[tid + it * 256] = ((const float4*)&g_h[i0][0])[tid + it * 256];
#pragma unroll
    for (int it = 0; it < 2; it++)
        ((float4*)ws)[tid + it * 256] = ((const float4*)W_out)[tid + it * 256];
    __syncthreads();
    const int r = tid >> 4, f = tid & 15;
    float acc = 0.f;
#pragma unroll 8
    for (int k = 0; k < HEADS * HID; k++) acc = fmaf(hs[r][k], ws[k][f], acc);
    g_Wh2[i0 + r][f] = acc;
}

// ---------------- K7: u2/v2 ----------------
__global__ void k_uv2(const float* __restrict__ a_out) {
    const int wid = threadIdx.x >> 5, lane = threadIdx.x & 31;
    const int i = blockIdx.x * 8 + wid;
    float pu = 0.f, pv = 0.f;
    if (lane < C) {
        float wh = g_Wh2[i][lane];
        pu = wh * a_out[lane];
        pv = wh * a_out[C + lane];
    }
#pragma unroll
    for (int o = 16; o; o >>= 1) {
        pu += __shfl_xor_sync(0xffffffffu, pu, o);
        pv += __shfl_xor_sync(0xffffffffu, pv, o);
    }
    if (lane == 0) { g_u2[i] = pu; g_v2[i] = pv; }
}

// ---------------- K8: exp tables (output layer) ----------------
__global__ void k_exp2() {
    const int i = blockIdx.x * 256 + threadIdx.x;
    const float um = g_max[4], vm = g_max[5], c = um + vm;
    const float u = g_u2[i], v = g_v2[i];
    g_A2[i]   = expf(u - um);
    g_A5K2[i] = expf(0.2f * (u - um) - 0.8f * c);
    g_B2[i]   = expf(v - vm);
    g_B52[i]  = expf(0.2f * (v - vm));
}

// ---------------- K9: output attention + elu + log_softmax ----------------
__launch_bounds__(256, 1)
__global__ void k_attn2(const int* __restrict__ adj, float* __restrict__ out) {
    __shared__ float wS[64][64];     // 16 KB
    __shared__ float whs[64][C];     // 4 KB
    __shared__ float rowd[3][64];    // u2, A2, A5K2
    __shared__ float Zs[64];
    __shared__ float os[64][C + 1];
    __shared__ float lse[64];

    const int tid = threadIdx.x;
    const int wb = tid >> 5, lane = tid & 31;
    const int i0 = blockIdx.x * 64;
    const int fcol = tid & 15;
    const int ig = tid >> 4;           // 0..15 -> rows ig*4..
    const int rowbase = i0 + wb * 8;

    if (tid < 64) {
        rowd[0][tid] = g_u2[i0 + tid];
        rowd[1][tid] = g_A2[i0 + tid];
        rowd[2][tid] = g_A5K2[i0 + tid];
    }

    float acc[4] = {};
    float Zp[8] = {};

    int adjv[16];
    float vj[2], Bj[2], B5j[2];
    float4 whv;

    // prefetch tile 0
    {
        const int j0 = 0;
#pragma unroll
        for (int r = 0; r < 8; r++) {
            adjv[r * 2 + 0] = adj[(rowbase + r) * N + j0 + lane];
            adjv[r * 2 + 1] = adj[(rowbase + r) * N + j0 + 32 + lane];
        }
        int jc0 = j0 + lane, jc1 = j0 + 32 + lane;
        vj[0] = g_v2[jc0]; Bj[0] = g_B2[jc0]; B5j[0] = g_B52[jc0];
        vj[1] = g_v2[jc1]; Bj[1] = g_B2[jc1]; B5j[1] = g_B52[jc1];
        int jj = tid >> 2, ff = (tid & 3) * 4;
        whv = *(const float4*)&g_Wh2[j0 + jj][ff];
    }

    const int T = N / 64;  // 128 tiles
    for (int t = 0; t < T; t++) {
        __syncthreads();

        // phase A
        {
            int jj = tid >> 2, ff = (tid & 3) * 4;
            *(float4*)&whs[jj][ff] = whv;
        }
#pragma unroll
        for (int half = 0; half < 2; half++) {
            const int l2 = lane + half * 32;
            const float vv = vj[half], bb = Bj[half], b5 = B5j[half];
#pragma unroll
            for (int r = 0; r < 8; r++) {
                const int r8 = wb * 8 + r;
                float w = 0.f;
                if (adjv[r * 2 + half] != 0)
                    w = (rowd[0][r8] + vv > 0.f) ? rowd[1][r8] * bb : rowd[2][r8] * b5;
                wS[r8][l2] = w;
                Zp[r] += w;
            }
        }

        if (t + 1 < T) {
            const int j0 = (t + 1) * 64;
#pragma unroll
            for (int r = 0; r < 8; r++) {
                adjv[r * 2 + 0] = adj[(rowbase + r) * N + j0 + lane];
                adjv[r * 2 + 1] = adj[(rowbase + r) * N + j0 + 32 + lane];
            }
            int jc0 = j0 + lane, jc1 = j0 + 32 + lane;
            vj[0] = g_v2[jc0]; Bj[0] = g_B2[jc0]; B5j[0] = g_B52[jc0];
            vj[1] = g_v2[jc1]; Bj[1] = g_B2[jc1]; B5j[1] = g_B52[jc1];
            int jj = tid >> 2, ff = (tid & 3) * 4;
            whv = *(const float4*)&g_Wh2[j0 + jj][ff];
        }

        __syncthreads();

        // phase B: acc[4 rows] for feature fcol
        const float* wrow = &wS[ig * 4][0];
#pragma unroll 8
        for (int jj = 0; jj < 64; jj++) {
            float wh = whs[jj][fcol];
#pragma unroll
            for (int r = 0; r < 4; r++)
                acc[r] = fmaf(wrow[(r << 6) + jj], wh, acc[r]);
        }
    }

    // reduce Z across lanes (warp wb owns rows wb*8..wb*8+7)
#pragma unroll
    for (int r = 0; r < 8; r++) {
#pragma unroll
        for (int o = 16; o; o >>= 1) Zp[r] += __shfl_xor_sync(0xffffffffu, Zp[r], o);
    }
    if (lane == 0) {
        Zs[wb * 8 + 0] = Zp[0]; Zs[wb * 8 + 1] = Zp[1];
        Zs[wb * 8 + 2] = Zp[2]; Zs[wb * 8 + 3] = Zp[3];
        Zs[wb * 8 + 4] = Zp[4]; Zs[wb * 8 + 5] = Zp[5];
        Zs[wb * 8 + 6] = Zp[6]; Zs[wb * 8 + 7] = Zp[7];
    }
    __syncthreads();

    // normalize + elu
#pragma unroll
    for (int r = 0; r < 4; r++) {
        const int row = ig * 4 + r;
        float o = acc[r] / Zs[row];
        o = (o > 0.f) ? o : expm1f(o);
        os[row][fcol] = o;
    }
    __syncthreads();

    // per-row log-sum-exp
    if (tid < 64) {
        float m = -3.0e38f;
#pragma unroll
        for (int k = 0; k < C; k++) m = fmaxf(m, os[tid][k]);
        float s = 0.f;
#pragma unroll
        for (int k = 0; k < C; k++) s += expf(os[tid][k] - m);
        lse[tid] = m + logf(s);
    }
    __syncthreads();

#pragma unroll
    for (int r = 0; r < 4; r++) {
        const int row = ig * 4 + r;
        out[(i0 + row) * C + fcol] = os[row][fcol] - lse[row];
    }
}

// ---------------- launch ----------------
extern "C" void kernel_launch(void* const* d_in, const int* in_sizes, int n_in,
                              void* d_out, int out_size) {
    const float* x       = (const float*)d_in[0];
    const int*   adj     = (const int*)  d_in[1];
    const float* W_heads = (const float*)d_in[2];
    const float* a_heads = (const float*)d_in[3];
    const float* W_out   = (const float*)d_in[4];
    const float* a_out   = (const float*)d_in[5];
    float* out = (float*)d_out;

    k_gemm1<<<dim3(N / 64, HEADS), 256>>>(x, W_heads);
    k_uv1<<<dim3(N / 8, HEADS), 256>>>(a_heads);
    k_max<<<4, 1024>>>(0);
    k_exp1<<<dim3(N / 256, HEADS), 256>>>();
    k_attn1<<<N / 64, 256>>>(adj);
    k_gemm2<<<N / 16, 256>>>(W_out);
    k_uv2<<<N / 8, 256>>>(a_out);
    k_max<<<2, 1024>>>(4);
    k_exp2<<<N / 256, 256>>>();
    k_attn2<<<N / 64, 256>>>(adj, out);
}